// round 2
// baseline (speedup 1.0000x reference)
#include <cuda_runtime.h>

typedef unsigned long long ull;

#define NTHREADS 256
#define RAYS 8
#define NBLOCKS 4096          // 32768 / 8
#define B_TOTAL 32768

// dynamic shared layout (in floats)
#define OFF_W    0            // 64x64 weight staging      (4096)
#define OFF_OUT  4096         // per-ray out state 8x(8x64)(4096)
#define OFF_A    8192         // per-ray attn accum        (4096)
#define OFF_QKV  12288        // per-ray Q,K,V 8x3x(8x64)  (12288)
#define OFF_P    24576        // per-ray probs/query 8x64  (512)
#define SMEM_FLOATS 25088
#define SMEM_BYTES  (SMEM_FLOATS * 4)

struct Params {
  const float *query, *latent, *W1, *b1;
  const float *Wq, *bq, *Wk, *bk, *Wv, *bv, *Wo, *bo;
  const float *fW1, *fb1, *fW2, *fb2, *g1, *be1, *g2, *be2;
  const float *cWq, *cbq, *cWk, *cbk, *cWv, *cbv, *cWo, *cbo;
  const float *Wc, *bc, *Ws, *bs;
  float *o_color, *o_sigma, *o_out, *o_attn;
};

__device__ __forceinline__ ull ffma2(ull a, ull b, ull c) {
  ull d;
  asm("fma.rn.f32x2 %0, %1, %2, %3;" : "=l"(d) : "l"(a), "l"(b), "l"(c));
  return d;
}
__device__ __forceinline__ ull pack2(float lo, float hi) {
  ull d;
  asm("mov.b64 %0, {%1, %2};" : "=l"(d) : "f"(lo), "f"(hi));
  return d;
}
__device__ __forceinline__ float2 unpack2(ull v) {
  float lo, hi;
  asm("mov.b64 {%0, %1}, %2;" : "=f"(lo), "=f"(hi) : "l"(v));
  return make_float2(lo, hi);
}

// dst(8x64)[:, c0:c0+2] = act(8x64) @ w(64x64), accumulated into packed
// even/odd partial sums. act rows stride 64 floats, 16B-aligned.
__device__ __forceinline__ void gemm8_core(const float* __restrict__ act,
                                           const float* __restrict__ w,
                                           int c0, ull acc0[8], ull acc1[8]) {
  #pragma unroll 2
  for (int d = 0; d < 64; d += 4) {
    float2 wa = *(const float2*)(w + (d + 0) * 64 + c0);
    float2 wb = *(const float2*)(w + (d + 1) * 64 + c0);
    float2 wc = *(const float2*)(w + (d + 2) * 64 + c0);
    float2 wd = *(const float2*)(w + (d + 3) * 64 + c0);
    ull wp00 = pack2(wa.x, wb.x);
    ull wp01 = pack2(wa.y, wb.y);
    ull wp10 = pack2(wc.x, wd.x);
    ull wp11 = pack2(wc.y, wd.y);
    #pragma unroll
    for (int s = 0; s < 8; s++) {
      ulonglong2 a = *(const ulonglong2*)(act + s * 64 + d);
      acc0[s] = ffma2(a.x, wp00, acc0[s]);
      acc1[s] = ffma2(a.x, wp01, acc1[s]);
      acc0[s] = ffma2(a.y, wp10, acc0[s]);
      acc1[s] = ffma2(a.y, wp11, acc1[s]);
    }
  }
}

// full projection with bias, optional relu, store to dst (warp-local rows)
__device__ __forceinline__ void proj_store(const float* act, const float* w,
                                           float b0, float b1, int c0,
                                           float* dst, int do_relu) {
  ull a0[8], a1[8];
  #pragma unroll
  for (int s = 0; s < 8; s++) { a0[s] = pack2(b0, 0.f); a1[s] = pack2(b1, 0.f); }
  gemm8_core(act, w, c0, a0, a1);
  #pragma unroll
  for (int s = 0; s < 8; s++) {
    float2 x = unpack2(a0[s]);
    float2 y = unpack2(a1[s]);
    float r0 = x.x + x.y, r1 = y.x + y.y;
    if (do_relu) { r0 = fmaxf(r0, 0.f); r1 = fmaxf(r1, 0.f); }
    dst[s * 64 + c0] = r0;
    dst[s * 64 + c0 + 1] = r1;
  }
}

// LayerNorm of v (8 rows, this lane holds cols c0,c0+1), write to dst
__device__ __forceinline__ void layernorm8(const float v[16], const float* g,
                                           const float* be, int c0, float* dst) {
  float gg0 = g[c0], gg1 = g[c0 + 1];
  float bb0 = be[c0], bb1 = be[c0 + 1];
  #pragma unroll
  for (int s = 0; s < 8; s++) {
    float sum = v[2 * s] + v[2 * s + 1];
    #pragma unroll
    for (int o = 16; o > 0; o >>= 1) sum += __shfl_xor_sync(0xffffffffu, sum, o);
    float mean = sum * 0.015625f;
    float d0 = v[2 * s] - mean, d1 = v[2 * s + 1] - mean;
    float vs = d0 * d0 + d1 * d1;
    #pragma unroll
    for (int o = 16; o > 0; o >>= 1) vs += __shfl_xor_sync(0xffffffffu, vs, o);
    float rstd = rsqrtf(vs * 0.015625f + 1e-5f);
    dst[s * 64 + c0] = d0 * rstd * gg0 + bb0;
    dst[s * 64 + c0 + 1] = d1 * rstd * gg1 + bb1;
  }
}

#define STAGE(SRC, STRIDE)                                        \
  do {                                                            \
    const float* _s = (SRC);                                      \
    for (int i_ = tid; i_ < 4096; i_ += NTHREADS) {               \
      int d_ = i_ >> 6, j_ = i_ & 63;                             \
      s_w[i_] = _s[d_ * (STRIDE) + j_];                           \
    }                                                             \
  } while (0)

__global__ void __launch_bounds__(NTHREADS, 2) rt_kernel(Params p) {
  extern __shared__ float sm[];
  const int tid = threadIdx.x;
  const int warp = tid >> 5, lane = tid & 31;
  const int c0 = lane * 2;
  const int b = blockIdx.x * RAYS + warp;

  float* s_w = sm + OFF_W;
  float* s_out = sm + OFF_OUT;
  float* s_a = sm + OFF_A;
  float* s_qkv = sm + OFF_QKV;
  float* s_p = sm + OFF_P;

  float* my_out = s_out + warp * 512;
  float* my_a = s_a + warp * 512;
  float* my_q = s_qkv + warp * 1536;
  float* my_k = my_q + 512;
  float* my_v = my_q + 1024;
  float* my_p = s_p + warp * 64;

  // ---------------- stage 0: out = relu(latent @ W1 + b1) ----------------
  {
    ull a0[8], a1[8];
    float b0v = p.b1[c0], b1v = p.b1[c0 + 1];
    #pragma unroll
    for (int s = 0; s < 8; s++) { a0[s] = pack2(b0v, 0.f); a1[s] = pack2(b1v, 0.f); }
    float* s_lat = s_qkv;  // reuse QKV space as latent chunk staging
    for (int kc = 0; kc < 8; kc++) {
      for (int i = tid; i < 4096; i += NTHREADS) s_w[i] = p.W1[kc * 4096 + i];
      for (int i = tid; i < 4096; i += NTHREADS) {
        int r = i >> 9, rem = i & 511, s = rem >> 6, d = rem & 63;
        s_lat[i] = p.latent[(size_t)(blockIdx.x * RAYS + r) * 4096 +
                            (size_t)s * 512 + kc * 64 + d];
      }
      __syncthreads();
      gemm8_core(s_lat + warp * 512, s_w, c0, a0, a1);
      __syncthreads();
    }
    #pragma unroll
    for (int s = 0; s < 8; s++) {
      float2 x = unpack2(a0[s]);
      float2 y = unpack2(a1[s]);
      my_out[s * 64 + c0] = fmaxf(x.x + x.y, 0.f);
      my_out[s * 64 + c0 + 1] = fmaxf(y.x + y.y, 0.f);
    }
  }

  // ---------------- 4 transformer layers ----------------
  for (int l = 0; l < 4; l++) {
    for (int h = 0; h < 4; h++) {
      // Q projection (head column block)
      STAGE(p.Wq + l * 16384 + h * 64, 256);
      __syncthreads();
      proj_store(my_out, s_w, p.bq[l * 256 + h * 64 + c0],
                 p.bq[l * 256 + h * 64 + c0 + 1], c0, my_q, 0);
      __syncthreads();
      // K
      STAGE(p.Wk + l * 16384 + h * 64, 256);
      __syncthreads();
      proj_store(my_out, s_w, p.bk[l * 256 + h * 64 + c0],
                 p.bk[l * 256 + h * 64 + c0 + 1], c0, my_k, 0);
      __syncthreads();
      // V
      STAGE(p.Wv + l * 16384 + h * 64, 256);
      __syncthreads();
      proj_store(my_out, s_w, p.bv[l * 256 + h * 64 + c0],
                 p.bv[l * 256 + h * 64 + c0 + 1], c0, my_v, 0);
      __syncthreads();

      // ---- attention (8x8, warp-local) ----
      {
        float pr[2];
        #pragma unroll
        for (int u = 0; u < 2; u++) {
          int idx = lane + u * 32;
          int q = idx >> 3, k = idx & 7;
          float sum = 0.f;
          #pragma unroll 8
          for (int j = 0; j < 64; j += 2) {
            float2 qq = *(const float2*)(my_q + q * 64 + j);
            float2 kk = *(const float2*)(my_k + k * 64 + j);
            sum = fmaf(qq.x, kk.x, sum);
            sum = fmaf(qq.y, kk.y, sum);
          }
          float sc = sum * 0.125f;
          float m = sc;
          m = fmaxf(m, __shfl_xor_sync(0xffffffffu, m, 1));
          m = fmaxf(m, __shfl_xor_sync(0xffffffffu, m, 2));
          m = fmaxf(m, __shfl_xor_sync(0xffffffffu, m, 4));
          float e = expf(sc - m);
          float se = e;
          se += __shfl_xor_sync(0xffffffffu, se, 1);
          se += __shfl_xor_sync(0xffffffffu, se, 2);
          se += __shfl_xor_sync(0xffffffffu, se, 4);
          pr[u] = e / se;
        }
        my_p[lane] = pr[0];
        my_p[lane + 32] = pr[1];
        {
          size_t ab = (size_t)b * 1024 + (size_t)l * 256 + h * 64;
          p.o_attn[ab + lane] = pr[0];
          p.o_attn[ab + lane + 32] = pr[1];
        }
        __syncwarp();
        // context = prob @ V   (this lane: cols c0,c0+1, all 8 q rows)
        float cx[16];
        #pragma unroll
        for (int i = 0; i < 16; i++) cx[i] = 0.f;
        #pragma unroll
        for (int k = 0; k < 8; k++) {
          float2 v = *(const float2*)(my_v + k * 64 + c0);
          #pragma unroll
          for (int q = 0; q < 8; q++) {
            float pk = my_p[q * 8 + k];
            cx[2 * q] = fmaf(pk, v.x, cx[2 * q]);
            cx[2 * q + 1] = fmaf(pk, v.y, cx[2 * q + 1]);
          }
        }
        __syncwarp();
        #pragma unroll
        for (int q = 0; q < 8; q++) {
          my_q[q * 64 + c0] = cx[2 * q];       // Q slot reused as context
          my_q[q * 64 + c0 + 1] = cx[2 * q + 1];
        }
        __syncwarp();
      }

      // ---- out-proj (head block of Wo), accumulate into s_a ----
      STAGE(p.Wo + l * 16384 + h * 4096, 64);
      __syncthreads();
      {
        ull a0[8], a1[8];
        if (h == 0) {
          float o0 = p.bo[l * 64 + c0], o1 = p.bo[l * 64 + c0 + 1];
          #pragma unroll
          for (int s = 0; s < 8; s++) { a0[s] = pack2(o0, 0.f); a1[s] = pack2(o1, 0.f); }
        } else {
          #pragma unroll
          for (int s = 0; s < 8; s++) {
            a0[s] = pack2(my_a[s * 64 + c0], 0.f);
            a1[s] = pack2(my_a[s * 64 + c0 + 1], 0.f);
          }
        }
        gemm8_core(my_q, s_w, c0, a0, a1);
        #pragma unroll
        for (int s = 0; s < 8; s++) {
          float2 x = unpack2(a0[s]);
          float2 y = unpack2(a1[s]);
          my_a[s * 64 + c0] = x.x + x.y;
          my_a[s * 64 + c0 + 1] = y.x + y.y;
        }
      }
      __syncthreads();
    }  // heads

    // ---- LN1: out = LN(a + out) ----
    {
      float v[16];
      #pragma unroll
      for (int s = 0; s < 8; s++) {
        v[2 * s] = my_a[s * 64 + c0] + my_out[s * 64 + c0];
        v[2 * s + 1] = my_a[s * 64 + c0 + 1] + my_out[s * 64 + c0 + 1];
      }
      layernorm8(v, p.g1 + l * 64, p.be1 + l * 64, c0, my_out);
    }
    // ---- FF1 ----
    STAGE(p.fW1 + l * 4096, 64);
    __syncthreads();   // also makes LN1's my_out writes warp/CTA-visible
    proj_store(my_out, s_w, p.fb1[l * 64 + c0], p.fb1[l * 64 + c0 + 1], c0, my_q, 1);
    __syncthreads();
    // ---- FF2 + LN2 ----
    STAGE(p.fW2 + l * 4096, 64);
    __syncthreads();
    {
      ull a0[8], a1[8];
      float f0 = p.fb2[l * 64 + c0], f1 = p.fb2[l * 64 + c0 + 1];
      #pragma unroll
      for (int s = 0; s < 8; s++) { a0[s] = pack2(f0, 0.f); a1[s] = pack2(f1, 0.f); }
      gemm8_core(my_q, s_w, c0, a0, a1);
      float v[16];
      #pragma unroll
      for (int s = 0; s < 8; s++) {
        float2 x = unpack2(a0[s]);
        float2 y = unpack2(a1[s]);
        v[2 * s] = x.x + x.y + my_out[s * 64 + c0];
        v[2 * s + 1] = y.x + y.y + my_out[s * 64 + c0 + 1];
      }
      layernorm8(v, p.g2 + l * 64, p.be2 + l * 64, c0, my_out);
    }
    __syncthreads();
  }  // layers

  // ---------------- sigma = max_s(out) @ Ws + bs ----------------
  {
    float m0 = my_out[c0], m1 = my_out[c0 + 1];
    #pragma unroll
    for (int s = 1; s < 8; s++) {
      m0 = fmaxf(m0, my_out[s * 64 + c0]);
      m1 = fmaxf(m1, my_out[s * 64 + c0 + 1]);
    }
    float part = m0 * p.Ws[c0] + m1 * p.Ws[c0 + 1];
    #pragma unroll
    for (int o = 16; o > 0; o >>= 1) part += __shfl_xor_sync(0xffffffffu, part, o);
    if (lane == 0) p.o_sigma[b] = part + p.bs[0];
  }

  // ---------------- write out state ----------------
  #pragma unroll
  for (int s = 0; s < 8; s++) {
    *(float2*)(p.o_out + (size_t)b * 512 + s * 64 + c0) =
        make_float2(my_out[s * 64 + c0], my_out[s * 64 + c0 + 1]);
  }

  // ---------------- cross attention + color ----------------
  my_p[c0] = p.query[(size_t)b * 64 + c0];
  my_p[c0 + 1] = p.query[(size_t)b * 64 + c0 + 1];
  __syncwarp();

  float ca0 = 0.f, ca1 = 0.f;
  for (int h = 0; h < 4; h++) {
    // cq = query @ cWq_h + cbq_h     (1 row)
    STAGE(p.cWq + h * 64, 256);
    __syncthreads();
    float cq0 = p.cbq[h * 64 + c0], cq1 = p.cbq[h * 64 + c0 + 1];
    #pragma unroll 8
    for (int d = 0; d < 64; d += 2) {
      float2 a = *(const float2*)(my_p + d);
      float2 w0 = *(const float2*)(s_w + d * 64 + c0);
      float2 w1 = *(const float2*)(s_w + (d + 1) * 64 + c0);
      cq0 = fmaf(a.x, w0.x, cq0);
      cq0 = fmaf(a.y, w1.x, cq0);
      cq1 = fmaf(a.x, w0.y, cq1);
      cq1 = fmaf(a.y, w1.y, cq1);
    }
    __syncthreads();
    // ck = out @ cWk_h + cbk_h
    STAGE(p.cWk + h * 64, 256);
    __syncthreads();
    proj_store(my_out, s_w, p.cbk[h * 64 + c0], p.cbk[h * 64 + c0 + 1], c0, my_k, 0);
    __syncthreads();
    // cv
    STAGE(p.cWv + h * 64, 256);
    __syncthreads();
    proj_store(my_out, s_w, p.cbv[h * 64 + c0], p.cbv[h * 64 + c0 + 1], c0, my_v, 0);
    __syncthreads();
    // scores over 8 keys (warp-reduced dots), softmax, ctx
    float e[8];
    #pragma unroll
    for (int k = 0; k < 8; k++) {
      float pk = cq0 * my_k[k * 64 + c0] + cq1 * my_k[k * 64 + c0 + 1];
      #pragma unroll
      for (int o = 16; o > 0; o >>= 1) pk += __shfl_xor_sync(0xffffffffu, pk, o);
      e[k] = pk * 0.125f;
    }
    float mm = e[0];
    #pragma unroll
    for (int k = 1; k < 8; k++) mm = fmaxf(mm, e[k]);
    float prb[8], sum = 0.f;
    #pragma unroll
    for (int k = 0; k < 8; k++) { prb[k] = expf(e[k] - mm); sum += prb[k]; }
    float inv = 1.f / sum;
    float cx0 = 0.f, cx1 = 0.f;
    #pragma unroll
    for (int k = 0; k < 8; k++) {
      float2 v = *(const float2*)(my_v + k * 64 + c0);
      float pk = prb[k] * inv;
      cx0 = fmaf(pk, v.x, cx0);
      cx1 = fmaf(pk, v.y, cx1);
    }
    my_q[c0] = cx0;
    my_q[c0 + 1] = cx1;
    __syncwarp();
    // ca += ctx @ cWo_h   (+ cbo at h==0)
    STAGE(p.cWo + h * 4096, 64);
    __syncthreads();
    if (h == 0) { ca0 = p.cbo[c0]; ca1 = p.cbo[c0 + 1]; }
    #pragma unroll 8
    for (int d = 0; d < 64; d += 2) {
      float2 a = *(const float2*)(my_q + d);
      float2 w0 = *(const float2*)(s_w + d * 64 + c0);
      float2 w1 = *(const float2*)(s_w + (d + 1) * 64 + c0);
      ca0 = fmaf(a.x, w0.x, ca0);
      ca0 = fmaf(a.y, w1.x, ca0);
      ca1 = fmaf(a.x, w0.y, ca1);
      ca1 = fmaf(a.y, w1.y, ca1);
    }
    __syncthreads();
  }

  // color = relu(ca) @ Wc + bc
  {
    float r0 = fmaxf(ca0, 0.f), r1 = fmaxf(ca1, 0.f);
    #pragma unroll
    for (int t = 0; t < 3; t++) {
      float part = r0 * p.Wc[c0 * 3 + t] + r1 * p.Wc[(c0 + 1) * 3 + t];
      #pragma unroll
      for (int o = 16; o > 0; o >>= 1) part += __shfl_xor_sync(0xffffffffu, part, o);
      if (lane == 0) p.o_color[(size_t)b * 3 + t] = part + p.bc[t];
    }
  }
}

extern "C" void kernel_launch(void* const* d_in, const int* in_sizes, int n_in,
                              void* d_out, int out_size) {
  Params p;
  p.query = (const float*)d_in[0];
  p.latent = (const float*)d_in[1];
  p.W1 = (const float*)d_in[2];
  p.b1 = (const float*)d_in[3];
  p.Wq = (const float*)d_in[4];
  p.bq = (const float*)d_in[5];
  p.Wk = (const float*)d_in[6];
  p.bk = (const float*)d_in[7];
  p.Wv = (const float*)d_in[8];
  p.bv = (const float*)d_in[9];
  p.Wo = (const float*)d_in[10];
  p.bo = (const float*)d_in[11];
  p.fW1 = (const float*)d_in[12];
  p.fb1 = (const float*)d_in[13];
  p.fW2 = (const float*)d_in[14];
  p.fb2 = (const float*)d_in[15];
  p.g1 = (const float*)d_in[16];
  p.be1 = (const float*)d_in[17];
  p.g2 = (const float*)d_in[18];
  p.be2 = (const float*)d_in[19];
  p.cWq = (const float*)d_in[20];
  p.cbq = (const float*)d_in[21];
  p.cWk = (const float*)d_in[22];
  p.cbk = (const float*)d_in[23];
  p.cWv = (const float*)d_in[24];
  p.cbv = (const float*)d_in[25];
  p.cWo = (const float*)d_in[26];
  p.cbo = (const float*)d_in[27];
  p.Wc = (const float*)d_in[28];
  p.bc = (const float*)d_in[29];
  p.Ws = (const float*)d_in[30];
  p.bs = (const float*)d_in[31];

  float* o = (float*)d_out;
  p.o_color = o;                                    // [B,1,3]
  p.o_sigma = o + (size_t)B_TOTAL * 3;              // [B,1]
  p.o_out = o + (size_t)B_TOTAL * 4;                // [B,8,64]
  p.o_attn = o + (size_t)B_TOTAL * 4 + (size_t)B_TOTAL * 512;  // [B,4,4,8,8]

  cudaFuncSetAttribute(rt_kernel, cudaFuncAttributeMaxDynamicSharedMemorySize,
                       SMEM_BYTES);
  rt_kernel<<<NBLOCKS, NTHREADS, SMEM_BYTES>>>(p);
}

// round 3
// speedup vs baseline: 1.0620x; 1.0620x over previous
#include <cuda_runtime.h>

typedef unsigned long long ull;

#define NTHREADS 256
#define RAYS 8
#define NBLOCKS 4096          // 32768 / 8
#define B_TOTAL 32768

// dynamic shared layout (in floats)
#define OFF_W    0            // 64x64 weight staging      (4096)
#define OFF_OUT  4096         // per-ray out state 8x(8x64)(4096)
#define OFF_A    8192         // per-ray attn accum        (4096)
#define OFF_QKV  12288        // per-ray Q,K,V 8x3x(8x64)  (12288)
#define OFF_P    24576        // per-ray probs/query 8x64  (512)
#define SMEM_FLOATS 25088
#define SMEM_BYTES  (SMEM_FLOATS * 4)

struct Params {
  const float *query, *latent, *W1, *b1;
  const float *Wq, *bq, *Wk, *bk, *Wv, *bv, *Wo, *bo;
  const float *fW1, *fb1, *fW2, *fb2, *g1, *be1, *g2, *be2;
  const float *cWq, *cbq, *cWk, *cbk, *cWv, *cbv, *cWo, *cbo;
  const float *Wc, *bc, *Ws, *bs;
  float *o_color, *o_sigma, *o_out, *o_attn;
};

__device__ __forceinline__ ull ffma2(ull a, ull b, ull c) {
  ull d;
  asm("fma.rn.f32x2 %0, %1, %2, %3;" : "=l"(d) : "l"(a), "l"(b), "l"(c));
  return d;
}
__device__ __forceinline__ ull pack2(float lo, float hi) {
  ull d;
  asm("mov.b64 %0, {%1, %2};" : "=l"(d) : "f"(lo), "f"(hi));
  return d;
}
__device__ __forceinline__ float2 unpack2(ull v) {
  float lo, hi;
  asm("mov.b64 {%0, %1}, %2;" : "=f"(lo), "=f"(hi) : "l"(v));
  return make_float2(lo, hi);
}

// dst(8x64)[:, c0:c0+2] = act(8x64) @ w(64x64), accumulated into packed
// even/odd partial sums. act rows stride 64 floats, 16B-aligned.
__device__ __forceinline__ void gemm8_core(const float* __restrict__ act,
                                           const float* __restrict__ w,
                                           int c0, ull acc0[8], ull acc1[8]) {
  #pragma unroll 2
  for (int d = 0; d < 64; d += 4) {
    float2 wa = *(const float2*)(w + (d + 0) * 64 + c0);
    float2 wb = *(const float2*)(w + (d + 1) * 64 + c0);
    float2 wc = *(const float2*)(w + (d + 2) * 64 + c0);
    float2 wd = *(const float2*)(w + (d + 3) * 64 + c0);
    ull wp00 = pack2(wa.x, wb.x);
    ull wp01 = pack2(wa.y, wb.y);
    ull wp10 = pack2(wc.x, wd.x);
    ull wp11 = pack2(wc.y, wd.y);
    #pragma unroll
    for (int s = 0; s < 8; s++) {
      ulonglong2 a = *(const ulonglong2*)(act + s * 64 + d);
      acc0[s] = ffma2(a.x, wp00, acc0[s]);
      acc1[s] = ffma2(a.x, wp01, acc1[s]);
      acc0[s] = ffma2(a.y, wp10, acc0[s]);
      acc1[s] = ffma2(a.y, wp11, acc1[s]);
    }
  }
}

// full projection with bias, optional relu, store to dst (warp-local rows)
__device__ __forceinline__ void proj_store(const float* act, const float* w,
                                           float b0, float b1, int c0,
                                           float* dst, int do_relu) {
  ull a0[8], a1[8];
  #pragma unroll
  for (int s = 0; s < 8; s++) { a0[s] = pack2(b0, 0.f); a1[s] = pack2(b1, 0.f); }
  gemm8_core(act, w, c0, a0, a1);
  #pragma unroll
  for (int s = 0; s < 8; s++) {
    float2 x = unpack2(a0[s]);
    float2 y = unpack2(a1[s]);
    float r0 = x.x + x.y, r1 = y.x + y.y;
    if (do_relu) { r0 = fmaxf(r0, 0.f); r1 = fmaxf(r1, 0.f); }
    dst[s * 64 + c0] = r0;
    dst[s * 64 + c0 + 1] = r1;
  }
}

// LayerNorm of v (8 rows, this lane holds cols c0,c0+1), write to dst
__device__ __forceinline__ void layernorm8(const float v[16], const float* g,
                                           const float* be, int c0, float* dst) {
  float gg0 = g[c0], gg1 = g[c0 + 1];
  float bb0 = be[c0], bb1 = be[c0 + 1];
  #pragma unroll
  for (int s = 0; s < 8; s++) {
    float sum = v[2 * s] + v[2 * s + 1];
    #pragma unroll
    for (int o = 16; o > 0; o >>= 1) sum += __shfl_xor_sync(0xffffffffu, sum, o);
    float mean = sum * 0.015625f;
    float d0 = v[2 * s] - mean, d1 = v[2 * s + 1] - mean;
    float vs = d0 * d0 + d1 * d1;
    #pragma unroll
    for (int o = 16; o > 0; o >>= 1) vs += __shfl_xor_sync(0xffffffffu, vs, o);
    float rstd = rsqrtf(vs * 0.015625f + 1e-5f);
    dst[s * 64 + c0] = d0 * rstd * gg0 + bb0;
    dst[s * 64 + c0 + 1] = d1 * rstd * gg1 + bb1;
  }
}

#define STAGE(SRC, STRIDE)                                        \
  do {                                                            \
    const float* _s = (SRC);                                      \
    for (int i_ = tid; i_ < 4096; i_ += NTHREADS) {               \
      int d_ = i_ >> 6, j_ = i_ & 63;                             \
      s_w[i_] = _s[d_ * (STRIDE) + j_];                           \
    }                                                             \
  } while (0)

__global__ void __launch_bounds__(NTHREADS, 2) rt_kernel(Params p) {
  extern __shared__ float sm[];
  const int tid = threadIdx.x;
  const int warp = tid >> 5, lane = tid & 31;
  const int c0 = lane * 2;
  const int b = blockIdx.x * RAYS + warp;

  float* s_w = sm + OFF_W;
  float* s_out = sm + OFF_OUT;
  float* s_a = sm + OFF_A;
  float* s_qkv = sm + OFF_QKV;
  float* s_p = sm + OFF_P;

  float* my_out = s_out + warp * 512;
  float* my_a = s_a + warp * 512;
  float* my_q = s_qkv + warp * 1536;
  float* my_k = my_q + 512;
  float* my_v = my_q + 1024;
  float* my_p = s_p + warp * 64;

  // ---------------- stage 0: out = relu(latent @ W1 + b1) ----------------
  {
    ull a0[8], a1[8];
    float b0v = p.b1[c0], b1v = p.b1[c0 + 1];
    #pragma unroll
    for (int s = 0; s < 8; s++) { a0[s] = pack2(b0v, 0.f); a1[s] = pack2(b1v, 0.f); }
    float* s_lat = s_qkv;  // reuse QKV space as latent chunk staging
    for (int kc = 0; kc < 8; kc++) {
      for (int i = tid; i < 4096; i += NTHREADS) s_w[i] = p.W1[kc * 4096 + i];
      for (int i = tid; i < 4096; i += NTHREADS) {
        int r = i >> 9, rem = i & 511, s = rem >> 6, d = rem & 63;
        s_lat[i] = p.latent[(size_t)(blockIdx.x * RAYS + r) * 4096 +
                            (size_t)s * 512 + kc * 64 + d];
      }
      __syncthreads();
      gemm8_core(s_lat + warp * 512, s_w, c0, a0, a1);
      __syncthreads();
    }
    #pragma unroll
    for (int s = 0; s < 8; s++) {
      float2 x = unpack2(a0[s]);
      float2 y = unpack2(a1[s]);
      my_out[s * 64 + c0] = fmaxf(x.x + x.y, 0.f);
      my_out[s * 64 + c0 + 1] = fmaxf(y.x + y.y, 0.f);
    }
  }

  // ---------------- 4 transformer layers ----------------
  for (int l = 0; l < 4; l++) {
    for (int h = 0; h < 4; h++) {
      // Q projection (head column block)
      STAGE(p.Wq + l * 16384 + h * 64, 256);
      __syncthreads();
      proj_store(my_out, s_w, p.bq[l * 256 + h * 64 + c0],
                 p.bq[l * 256 + h * 64 + c0 + 1], c0, my_q, 0);
      __syncthreads();
      // K
      STAGE(p.Wk + l * 16384 + h * 64, 256);
      __syncthreads();
      proj_store(my_out, s_w, p.bk[l * 256 + h * 64 + c0],
                 p.bk[l * 256 + h * 64 + c0 + 1], c0, my_k, 0);
      __syncthreads();
      // V
      STAGE(p.Wv + l * 16384 + h * 64, 256);
      __syncthreads();
      proj_store(my_out, s_w, p.bv[l * 256 + h * 64 + c0],
                 p.bv[l * 256 + h * 64 + c0 + 1], c0, my_v, 0);
      __syncthreads();

      // ---- attention (8x8, warp-local) ----
      {
        float pr[2];
        #pragma unroll
        for (int u = 0; u < 2; u++) {
          int idx = lane + u * 32;
          int q = idx >> 3, k = idx & 7;
          float sum = 0.f;
          #pragma unroll 8
          for (int j = 0; j < 64; j += 2) {
            float2 qq = *(const float2*)(my_q + q * 64 + j);
            float2 kk = *(const float2*)(my_k + k * 64 + j);
            sum = fmaf(qq.x, kk.x, sum);
            sum = fmaf(qq.y, kk.y, sum);
          }
          float sc = sum * 0.125f;
          float m = sc;
          m = fmaxf(m, __shfl_xor_sync(0xffffffffu, m, 1));
          m = fmaxf(m, __shfl_xor_sync(0xffffffffu, m, 2));
          m = fmaxf(m, __shfl_xor_sync(0xffffffffu, m, 4));
          float e = expf(sc - m);
          float se = e;
          se += __shfl_xor_sync(0xffffffffu, se, 1);
          se += __shfl_xor_sync(0xffffffffu, se, 2);
          se += __shfl_xor_sync(0xffffffffu, se, 4);
          pr[u] = e / se;
        }
        my_p[lane] = pr[0];
        my_p[lane + 32] = pr[1];
        {
          size_t ab = (size_t)b * 1024 + (size_t)l * 256 + h * 64;
          p.o_attn[ab + lane] = pr[0];
          p.o_attn[ab + lane + 32] = pr[1];
        }
        __syncwarp();
        // context = prob @ V   (this lane: cols c0,c0+1, all 8 q rows)
        float cx[16];
        #pragma unroll
        for (int i = 0; i < 16; i++) cx[i] = 0.f;
        #pragma unroll
        for (int k = 0; k < 8; k++) {
          float2 v = *(const float2*)(my_v + k * 64 + c0);
          #pragma unroll
          for (int q = 0; q < 8; q++) {
            float pk = my_p[q * 8 + k];
            cx[2 * q] = fmaf(pk, v.x, cx[2 * q]);
            cx[2 * q + 1] = fmaf(pk, v.y, cx[2 * q + 1]);
          }
        }
        __syncwarp();
        #pragma unroll
        for (int q = 0; q < 8; q++) {
          my_q[q * 64 + c0] = cx[2 * q];       // Q slot reused as context
          my_q[q * 64 + c0 + 1] = cx[2 * q + 1];
        }
        __syncwarp();
      }

      // ---- out-proj (head block of Wo), accumulate into s_a ----
      STAGE(p.Wo + l * 16384 + h * 4096, 64);
      __syncthreads();
      {
        ull a0[8], a1[8];
        if (h == 0) {
          float o0 = p.bo[l * 64 + c0], o1 = p.bo[l * 64 + c0 + 1];
          #pragma unroll
          for (int s = 0; s < 8; s++) { a0[s] = pack2(o0, 0.f); a1[s] = pack2(o1, 0.f); }
        } else {
          #pragma unroll
          for (int s = 0; s < 8; s++) {
            a0[s] = pack2(my_a[s * 64 + c0], 0.f);
            a1[s] = pack2(my_a[s * 64 + c0 + 1], 0.f);
          }
        }
        gemm8_core(my_q, s_w, c0, a0, a1);
        #pragma unroll
        for (int s = 0; s < 8; s++) {
          float2 x = unpack2(a0[s]);
          float2 y = unpack2(a1[s]);
          my_a[s * 64 + c0] = x.x + x.y;
          my_a[s * 64 + c0 + 1] = y.x + y.y;
        }
      }
      __syncthreads();
    }  // heads

    // ---- LN1: out = LN(a + out) ----
    {
      float v[16];
      #pragma unroll
      for (int s = 0; s < 8; s++) {
        v[2 * s] = my_a[s * 64 + c0] + my_out[s * 64 + c0];
        v[2 * s + 1] = my_a[s * 64 + c0 + 1] + my_out[s * 64 + c0 + 1];
      }
      layernorm8(v, p.g1 + l * 64, p.be1 + l * 64, c0, my_out);
    }
    // ---- FF1 ----
    STAGE(p.fW1 + l * 4096, 64);
    __syncthreads();   // also makes LN1's my_out writes warp/CTA-visible
    proj_store(my_out, s_w, p.fb1[l * 64 + c0], p.fb1[l * 64 + c0 + 1], c0, my_q, 1);
    __syncthreads();
    // ---- FF2 + LN2 ----
    STAGE(p.fW2 + l * 4096, 64);
    __syncthreads();
    {
      ull a0[8], a1[8];
      float f0 = p.fb2[l * 64 + c0], f1 = p.fb2[l * 64 + c0 + 1];
      #pragma unroll
      for (int s = 0; s < 8; s++) { a0[s] = pack2(f0, 0.f); a1[s] = pack2(f1, 0.f); }
      gemm8_core(my_q, s_w, c0, a0, a1);
      float v[16];
      #pragma unroll
      for (int s = 0; s < 8; s++) {
        float2 x = unpack2(a0[s]);
        float2 y = unpack2(a1[s]);
        v[2 * s] = x.x + x.y + my_out[s * 64 + c0];
        v[2 * s + 1] = y.x + y.y + my_out[s * 64 + c0 + 1];
      }
      layernorm8(v, p.g2 + l * 64, p.be2 + l * 64, c0, my_out);
    }
    __syncthreads();
  }  // layers

  // ---------------- sigma = max_s(out) @ Ws + bs ----------------
  {
    float m0 = my_out[c0], m1 = my_out[c0 + 1];
    #pragma unroll
    for (int s = 1; s < 8; s++) {
      m0 = fmaxf(m0, my_out[s * 64 + c0]);
      m1 = fmaxf(m1, my_out[s * 64 + c0 + 1]);
    }
    float part = m0 * p.Ws[c0] + m1 * p.Ws[c0 + 1];
    #pragma unroll
    for (int o = 16; o > 0; o >>= 1) part += __shfl_xor_sync(0xffffffffu, part, o);
    if (lane == 0) p.o_sigma[b] = part + p.bs[0];
  }

  // ---------------- write out state ----------------
  #pragma unroll
  for (int s = 0; s < 8; s++) {
    *(float2*)(p.o_out + (size_t)b * 512 + s * 64 + c0) =
        make_float2(my_out[s * 64 + c0], my_out[s * 64 + c0 + 1]);
  }

  // ---------------- cross attention + color ----------------
  my_p[c0] = p.query[(size_t)b * 64 + c0];
  my_p[c0 + 1] = p.query[(size_t)b * 64 + c0 + 1];
  __syncwarp();

  float ca0 = 0.f, ca1 = 0.f;
  for (int h = 0; h < 4; h++) {
    // cq = query @ cWq_h + cbq_h     (1 row)
    STAGE(p.cWq + h * 64, 256);
    __syncthreads();
    float cq0 = p.cbq[h * 64 + c0], cq1 = p.cbq[h * 64 + c0 + 1];
    #pragma unroll 8
    for (int d = 0; d < 64; d += 2) {
      float2 a = *(const float2*)(my_p + d);
      float2 w0 = *(const float2*)(s_w + d * 64 + c0);
      float2 w1 = *(const float2*)(s_w + (d + 1) * 64 + c0);
      cq0 = fmaf(a.x, w0.x, cq0);
      cq0 = fmaf(a.y, w1.x, cq0);
      cq1 = fmaf(a.x, w0.y, cq1);
      cq1 = fmaf(a.y, w1.y, cq1);
    }
    __syncthreads();
    // ck = out @ cWk_h + cbk_h
    STAGE(p.cWk + h * 64, 256);
    __syncthreads();
    proj_store(my_out, s_w, p.cbk[h * 64 + c0], p.cbk[h * 64 + c0 + 1], c0, my_k, 0);
    __syncthreads();
    // cv
    STAGE(p.cWv + h * 64, 256);
    __syncthreads();
    proj_store(my_out, s_w, p.cbv[h * 64 + c0], p.cbv[h * 64 + c0 + 1], c0, my_v, 0);
    __syncthreads();
    // scores over 8 keys (warp-reduced dots), softmax, ctx
    float e[8];
    #pragma unroll
    for (int k = 0; k < 8; k++) {
      float pk = cq0 * my_k[k * 64 + c0] + cq1 * my_k[k * 64 + c0 + 1];
      #pragma unroll
      for (int o = 16; o > 0; o >>= 1) pk += __shfl_xor_sync(0xffffffffu, pk, o);
      e[k] = pk * 0.125f;
    }
    float mm = e[0];
    #pragma unroll
    for (int k = 1; k < 8; k++) mm = fmaxf(mm, e[k]);
    float prb[8], sum = 0.f;
    #pragma unroll
    for (int k = 0; k < 8; k++) { prb[k] = expf(e[k] - mm); sum += prb[k]; }
    float inv = 1.f / sum;
    float cx0 = 0.f, cx1 = 0.f;
    #pragma unroll
    for (int k = 0; k < 8; k++) {
      float2 v = *(const float2*)(my_v + k * 64 + c0);
      float pk = prb[k] * inv;
      cx0 = fmaf(pk, v.x, cx0);
      cx1 = fmaf(pk, v.y, cx1);
    }
    my_q[c0] = cx0;
    my_q[c0 + 1] = cx1;
    __syncwarp();
    // ca += ctx @ cWo_h   (+ cbo at h==0)
    STAGE(p.cWo + h * 4096, 64);
    __syncthreads();
    if (h == 0) { ca0 = p.cbo[c0]; ca1 = p.cbo[c0 + 1]; }
    #pragma unroll 8
    for (int d = 0; d < 64; d += 2) {
      float2 a = *(const float2*)(my_q + d);
      float2 w0 = *(const float2*)(s_w + d * 64 + c0);
      float2 w1 = *(const float2*)(s_w + (d + 1) * 64 + c0);
      ca0 = fmaf(a.x, w0.x, ca0);
      ca0 = fmaf(a.y, w1.x, ca0);
      ca1 = fmaf(a.x, w0.y, ca1);
      ca1 = fmaf(a.y, w1.y, ca1);
    }
    __syncthreads();
  }

  // color = relu(ca) @ Wc + bc
  {
    float r0 = fmaxf(ca0, 0.f), r1 = fmaxf(ca1, 0.f);
    #pragma unroll
    for (int t = 0; t < 3; t++) {
      float part = r0 * p.Wc[c0 * 3 + t] + r1 * p.Wc[(c0 + 1) * 3 + t];
      #pragma unroll
      for (int o = 16; o > 0; o >>= 1) part += __shfl_xor_sync(0xffffffffu, part, o);
      if (lane == 0) p.o_color[(size_t)b * 3 + t] = part + p.bc[t];
    }
  }
}

extern "C" void kernel_launch(void* const* d_in, const int* in_sizes, int n_in,
                              void* d_out, int out_size) {
  Params p;
  p.query = (const float*)d_in[0];
  p.latent = (const float*)d_in[1];
  p.W1 = (const float*)d_in[2];
  p.b1 = (const float*)d_in[3];
  p.Wq = (const float*)d_in[4];
  p.bq = (const float*)d_in[5];
  p.Wk = (const float*)d_in[6];
  p.bk = (const float*)d_in[7];
  p.Wv = (const float*)d_in[8];
  p.bv = (const float*)d_in[9];
  p.Wo = (const float*)d_in[10];
  p.bo = (const float*)d_in[11];
  p.fW1 = (const float*)d_in[12];
  p.fb1 = (const float*)d_in[13];
  p.fW2 = (const float*)d_in[14];
  p.fb2 = (const float*)d_in[15];
  p.g1 = (const float*)d_in[16];
  p.be1 = (const float*)d_in[17];
  p.g2 = (const float*)d_in[18];
  p.be2 = (const float*)d_in[19];
  p.cWq = (const float*)d_in[20];
  p.cbq = (const float*)d_in[21];
  p.cWk = (const float*)d_in[22];
  p.cbk = (const float*)d_in[23];
  p.cWv = (const float*)d_in[24];
  p.cbv = (const float*)d_in[25];
  p.cWo = (const float*)d_in[26];
  p.cbo = (const float*)d_in[27];
  p.Wc = (const float*)d_in[28];
  p.bc = (const float*)d_in[29];
  p.Ws = (const float*)d_in[30];
  p.bs = (const float*)d_in[31];

  float* o = (float*)d_out;
  p.o_color = o;                                    // [B,1,3]
  p.o_sigma = o + (size_t)B_TOTAL * 3;              // [B,1]
  p.o_out = o + (size_t)B_TOTAL * 4;                // [B,8,64]
  p.o_attn = o + (size_t)B_TOTAL * 4 + (size_t)B_TOTAL * 512;  // [B,4,4,8,8]

  cudaFuncSetAttribute(rt_kernel, cudaFuncAttributeMaxDynamicSharedMemorySize,
                       SMEM_BYTES);
  rt_kernel<<<NBLOCKS, NTHREADS, SMEM_BYTES>>>(p);
}

// round 4
// speedup vs baseline: 1.3616x; 1.2821x over previous
#include <cuda_runtime.h>

typedef unsigned long long ull;

#define NTHREADS 256
#define RAYS 8
#define NBLOCKS 4096          // 32768 / 8
#define B_TOTAL 32768

#define WSTRIDE 68            // padded column stride (floats) for transposed weights

// dynamic shared layout (in floats)
#define OFF_W    0                       // transposed 64x64 weight staging (64*68 = 4352)
#define OFF_OUT  4352                    // per-ray out state 8x(8x64)  (4096)
#define OFF_A    (OFF_OUT + 4096)        // per-ray attn accum          (4096)
#define OFF_QKV  (OFF_A + 4096)          // per-ray Q,K,V 8x3x(8x64)    (12288)
#define OFF_P    (OFF_QKV + 12288)       // per-ray probs/query 8x64    (512)
#define SMEM_FLOATS (OFF_P + 512)
#define SMEM_BYTES  (SMEM_FLOATS * 4)

struct Params {
  const float *query, *latent, *W1, *b1;
  const float *Wq, *bq, *Wk, *bk, *Wv, *bv, *Wo, *bo;
  const float *fW1, *fb1, *fW2, *fb2, *g1, *be1, *g2, *be2;
  const float *cWq, *cbq, *cWk, *cbk, *cWv, *cbv, *cWo, *cbo;
  const float *Wc, *bc, *Ws, *bs;
  float *o_color, *o_sigma, *o_out, *o_attn;
};

__device__ __forceinline__ ull ffma2(ull a, ull b, ull c) {
  ull d;
  asm("fma.rn.f32x2 %0, %1, %2, %3;" : "=l"(d) : "l"(a), "l"(b), "l"(c));
  return d;
}
__device__ __forceinline__ ull pack2(float lo, float hi) {
  ull d;
  asm("mov.b64 %0, {%1, %2};" : "=l"(d) : "f"(lo), "f"(hi));
  return d;
}
__device__ __forceinline__ float2 unpack2(ull v) {
  float lo, hi;
  asm("mov.b64 {%0, %1}, %2;" : "=f"(lo), "=f"(hi) : "l"(v));
  return make_float2(lo, hi);
}

// dst(8x64)[:, {lane, lane+32}] = act(8x64) @ w(64x64), accumulated into
// packed even/odd-d partial sums. wt is TRANSPOSED+padded: wt[c*WSTRIDE + d].
// No register packing needed: operand pairs come straight from LDS.128.
__device__ __forceinline__ void gemm8t(const float* __restrict__ act,
                                       const float* __restrict__ wt,
                                       int lane, ull acc0[8], ull acc1[8]) {
  const float* w0 = wt + lane * WSTRIDE;
  const float* w1 = wt + (lane + 32) * WSTRIDE;
  #pragma unroll 2
  for (int d = 0; d < 64; d += 4) {
    ulonglong2 wp0 = *(const ulonglong2*)(w0 + d);  // (w[d][c0],w[d+1][c0]),(w[d+2],w[d+3])
    ulonglong2 wp1 = *(const ulonglong2*)(w1 + d);
    #pragma unroll
    for (int s = 0; s < 8; s++) {
      ulonglong2 a = *(const ulonglong2*)(act + s * 64 + d);  // broadcast
      acc0[s] = ffma2(a.x, wp0.x, acc0[s]);
      acc1[s] = ffma2(a.x, wp1.x, acc1[s]);
      acc0[s] = ffma2(a.y, wp0.y, acc0[s]);
      acc1[s] = ffma2(a.y, wp1.y, acc1[s]);
    }
  }
}

// full projection with bias, optional relu, store to dst (warp-local rows)
__device__ __forceinline__ void proj_store(const float* act, const float* wt,
                                           const float* bias, int lane,
                                           float* dst, int do_relu) {
  ull a0[8], a1[8];
  float b0 = bias[lane], b1 = bias[lane + 32];
  #pragma unroll
  for (int s = 0; s < 8; s++) { a0[s] = pack2(b0, 0.f); a1[s] = pack2(b1, 0.f); }
  gemm8t(act, wt, lane, a0, a1);
  #pragma unroll
  for (int s = 0; s < 8; s++) {
    float2 x = unpack2(a0[s]);
    float2 y = unpack2(a1[s]);
    float r0 = x.x + x.y, r1 = y.x + y.y;
    if (do_relu) { r0 = fmaxf(r0, 0.f); r1 = fmaxf(r1, 0.f); }
    dst[s * 64 + lane] = r0;
    dst[s * 64 + lane + 32] = r1;
  }
}

// LayerNorm of v (8 rows; this lane holds cols lane and lane+32), write to dst
__device__ __forceinline__ void layernorm8(const float v[16], const float* g,
                                           const float* be, int lane, float* dst) {
  float gg0 = g[lane], gg1 = g[lane + 32];
  float bb0 = be[lane], bb1 = be[lane + 32];
  #pragma unroll
  for (int s = 0; s < 8; s++) {
    float sum = v[2 * s] + v[2 * s + 1];
    #pragma unroll
    for (int o = 16; o > 0; o >>= 1) sum += __shfl_xor_sync(0xffffffffu, sum, o);
    float mean = sum * 0.015625f;
    float d0 = v[2 * s] - mean, d1 = v[2 * s + 1] - mean;
    float vs = d0 * d0 + d1 * d1;
    #pragma unroll
    for (int o = 16; o > 0; o >>= 1) vs += __shfl_xor_sync(0xffffffffu, vs, o);
    float rstd = rsqrtf(vs * 0.015625f + 1e-5f);
    dst[s * 64 + lane] = d0 * rstd * gg0 + bb0;
    dst[s * 64 + lane + 32] = d1 * rstd * gg1 + bb1;
  }
}

// stage a 64x64 weight block TRANSPOSED into s_w: s_w[j*WSTRIDE + d] = src[d*STRIDE + j]
// (global reads coalesced along j; STS has a benign 4-way conflict)
#define STAGET(SRC, STRIDE)                                       \
  do {                                                            \
    const float* _s = (SRC);                                      \
    for (int i_ = tid; i_ < 4096; i_ += NTHREADS) {               \
      int d_ = i_ >> 6, j_ = i_ & 63;                             \
      s_w[j_ * WSTRIDE + d_] = _s[d_ * (STRIDE) + j_];            \
    }                                                             \
  } while (0)

__global__ void __launch_bounds__(NTHREADS, 2) rt_kernel(Params p) {
  extern __shared__ float sm[];
  const int tid = threadIdx.x;
  const int warp = tid >> 5, lane = tid & 31;
  const int b = blockIdx.x * RAYS + warp;

  float* s_w = sm + OFF_W;
  float* s_out = sm + OFF_OUT;
  float* s_a = sm + OFF_A;
  float* s_qkv = sm + OFF_QKV;
  float* s_p = sm + OFF_P;

  float* my_out = s_out + warp * 512;
  float* my_a = s_a + warp * 512;
  float* my_q = s_qkv + warp * 1536;
  float* my_k = my_q + 512;
  float* my_v = my_q + 1024;
  float* my_p = s_p + warp * 64;

  // ---------------- stage 0: out = relu(latent @ W1 + b1) ----------------
  {
    ull a0[8], a1[8];
    float b0v = p.b1[lane], b1v = p.b1[lane + 32];
    #pragma unroll
    for (int s = 0; s < 8; s++) { a0[s] = pack2(b0v, 0.f); a1[s] = pack2(b1v, 0.f); }
    float* s_lat = s_qkv;  // reuse QKV space as latent chunk staging
    for (int kc = 0; kc < 8; kc++) {
      STAGET(p.W1 + kc * 4096, 64);
      for (int i = tid; i < 4096; i += NTHREADS) {
        int r = i >> 9, rem = i & 511, s = rem >> 6, d = rem & 63;
        s_lat[i] = p.latent[(size_t)(blockIdx.x * RAYS + r) * 4096 +
                            (size_t)s * 512 + kc * 64 + d];
      }
      __syncthreads();
      gemm8t(s_lat + warp * 512, s_w, lane, a0, a1);
      __syncthreads();
    }
    #pragma unroll
    for (int s = 0; s < 8; s++) {
      float2 x = unpack2(a0[s]);
      float2 y = unpack2(a1[s]);
      my_out[s * 64 + lane] = fmaxf(x.x + x.y, 0.f);
      my_out[s * 64 + lane + 32] = fmaxf(y.x + y.y, 0.f);
    }
  }

  // ---------------- 4 transformer layers ----------------
  for (int l = 0; l < 4; l++) {
    for (int h = 0; h < 4; h++) {
      // Q projection (head column block)
      STAGET(p.Wq + l * 16384 + h * 64, 256);
      __syncthreads();
      proj_store(my_out, s_w, p.bq + l * 256 + h * 64, lane, my_q, 0);
      __syncthreads();
      // K
      STAGET(p.Wk + l * 16384 + h * 64, 256);
      __syncthreads();
      proj_store(my_out, s_w, p.bk + l * 256 + h * 64, lane, my_k, 0);
      __syncthreads();
      // V
      STAGET(p.Wv + l * 16384 + h * 64, 256);
      __syncthreads();
      proj_store(my_out, s_w, p.bv + l * 256 + h * 64, lane, my_v, 0);
      __syncthreads();

      // ---- attention (8x8, warp-local) ----
      {
        float pr[2];
        #pragma unroll
        for (int u = 0; u < 2; u++) {
          int idx = lane + u * 32;
          int q = idx >> 3, k = idx & 7;
          const float* qr = my_q + q * 64;
          const float* kr = my_k + k * 64;
          ull acc = pack2(0.f, 0.f);
          #pragma unroll
          for (int j = 0; j < 64; j += 4) {
            ulonglong2 qq = *(const ulonglong2*)(qr + j);
            ulonglong2 kk = *(const ulonglong2*)(kr + j);
            acc = ffma2(qq.x, kk.x, acc);
            acc = ffma2(qq.y, kk.y, acc);
          }
          float2 t = unpack2(acc);
          float sc = (t.x + t.y) * 0.125f;
          float m = sc;
          m = fmaxf(m, __shfl_xor_sync(0xffffffffu, m, 1));
          m = fmaxf(m, __shfl_xor_sync(0xffffffffu, m, 2));
          m = fmaxf(m, __shfl_xor_sync(0xffffffffu, m, 4));
          float e = __expf(sc - m);
          float se = e;
          se += __shfl_xor_sync(0xffffffffu, se, 1);
          se += __shfl_xor_sync(0xffffffffu, se, 2);
          se += __shfl_xor_sync(0xffffffffu, se, 4);
          pr[u] = __fdividef(e, se);
        }
        my_p[lane] = pr[0];
        my_p[lane + 32] = pr[1];
        {
          size_t ab = (size_t)b * 1024 + (size_t)l * 256 + h * 64;
          p.o_attn[ab + lane] = pr[0];
          p.o_attn[ab + lane + 32] = pr[1];
        }
        __syncwarp();
        // context = prob @ V   (this lane: cols lane, lane+32, all 8 q rows)
        float cx[16];
        #pragma unroll
        for (int i = 0; i < 16; i++) cx[i] = 0.f;
        #pragma unroll
        for (int k = 0; k < 8; k++) {
          float vx = my_v[k * 64 + lane];
          float vy = my_v[k * 64 + lane + 32];
          #pragma unroll
          for (int q = 0; q < 8; q++) {
            float pk = my_p[q * 8 + k];
            cx[2 * q] = fmaf(pk, vx, cx[2 * q]);
            cx[2 * q + 1] = fmaf(pk, vy, cx[2 * q + 1]);
          }
        }
        __syncwarp();
        #pragma unroll
        for (int q = 0; q < 8; q++) {
          my_q[q * 64 + lane] = cx[2 * q];       // Q slot reused as context
          my_q[q * 64 + lane + 32] = cx[2 * q + 1];
        }
        __syncwarp();
      }

      // ---- out-proj (head block of Wo), accumulate into s_a ----
      STAGET(p.Wo + l * 16384 + h * 4096, 64);
      __syncthreads();
      {
        ull a0[8], a1[8];
        if (h == 0) {
          float o0 = p.bo[l * 64 + lane], o1 = p.bo[l * 64 + lane + 32];
          #pragma unroll
          for (int s = 0; s < 8; s++) { a0[s] = pack2(o0, 0.f); a1[s] = pack2(o1, 0.f); }
        } else {
          #pragma unroll
          for (int s = 0; s < 8; s++) {
            a0[s] = pack2(my_a[s * 64 + lane], 0.f);
            a1[s] = pack2(my_a[s * 64 + lane + 32], 0.f);
          }
        }
        gemm8t(my_q, s_w, lane, a0, a1);
        #pragma unroll
        for (int s = 0; s < 8; s++) {
          float2 x = unpack2(a0[s]);
          float2 y = unpack2(a1[s]);
          my_a[s * 64 + lane] = x.x + x.y;
          my_a[s * 64 + lane + 32] = y.x + y.y;
        }
      }
      __syncthreads();
    }  // heads

    // ---- LN1: out = LN(a + out) ----
    {
      float v[16];
      #pragma unroll
      for (int s = 0; s < 8; s++) {
        v[2 * s] = my_a[s * 64 + lane] + my_out[s * 64 + lane];
        v[2 * s + 1] = my_a[s * 64 + lane + 32] + my_out[s * 64 + lane + 32];
      }
      layernorm8(v, p.g1 + l * 64, p.be1 + l * 64, lane, my_out);
    }
    // ---- FF1 ----
    STAGET(p.fW1 + l * 4096, 64);
    __syncthreads();   // also makes LN1's my_out writes CTA-visible
    proj_store(my_out, s_w, p.fb1 + l * 64, lane, my_q, 1);
    __syncthreads();
    // ---- FF2 + LN2 ----
    STAGET(p.fW2 + l * 4096, 64);
    __syncthreads();
    {
      ull a0[8], a1[8];
      float f0 = p.fb2[l * 64 + lane], f1 = p.fb2[l * 64 + lane + 32];
      #pragma unroll
      for (int s = 0; s < 8; s++) { a0[s] = pack2(f0, 0.f); a1[s] = pack2(f1, 0.f); }
      gemm8t(my_q, s_w, lane, a0, a1);
      float v[16];
      #pragma unroll
      for (int s = 0; s < 8; s++) {
        float2 x = unpack2(a0[s]);
        float2 y = unpack2(a1[s]);
        v[2 * s] = x.x + x.y + my_out[s * 64 + lane];
        v[2 * s + 1] = y.x + y.y + my_out[s * 64 + lane + 32];
      }
      layernorm8(v, p.g2 + l * 64, p.be2 + l * 64, lane, my_out);
    }
    __syncthreads();
  }  // layers

  // ---------------- sigma = max_s(out) @ Ws + bs ----------------
  {
    float m0 = my_out[lane], m1 = my_out[lane + 32];
    #pragma unroll
    for (int s = 1; s < 8; s++) {
      m0 = fmaxf(m0, my_out[s * 64 + lane]);
      m1 = fmaxf(m1, my_out[s * 64 + lane + 32]);
    }
    float part = m0 * p.Ws[lane] + m1 * p.Ws[lane + 32];
    #pragma unroll
    for (int o = 16; o > 0; o >>= 1) part += __shfl_xor_sync(0xffffffffu, part, o);
    if (lane == 0) p.o_sigma[b] = part + p.bs[0];
  }

  // ---------------- write out state ----------------
  #pragma unroll
  for (int s = 0; s < 8; s++) {
    p.o_out[(size_t)b * 512 + s * 64 + lane] = my_out[s * 64 + lane];
    p.o_out[(size_t)b * 512 + s * 64 + lane + 32] = my_out[s * 64 + lane + 32];
  }

  // ---------------- cross attention + color ----------------
  my_p[lane] = p.query[(size_t)b * 64 + lane];
  my_p[lane + 32] = p.query[(size_t)b * 64 + lane + 32];
  __syncwarp();

  float ca0 = 0.f, ca1 = 0.f;
  for (int h = 0; h < 4; h++) {
    // cq = query @ cWq_h + cbq_h     (1 row)
    STAGET(p.cWq + h * 64, 256);
    __syncthreads();
    float cq0, cq1;
    {
      ull aq0 = pack2(p.cbq[h * 64 + lane], 0.f);
      ull aq1 = pack2(p.cbq[h * 64 + lane + 32], 0.f);
      const float* w0 = s_w + lane * WSTRIDE;
      const float* w1 = s_w + (lane + 32) * WSTRIDE;
      #pragma unroll
      for (int d = 0; d < 64; d += 4) {
        ulonglong2 a = *(const ulonglong2*)(my_p + d);
        ulonglong2 wp0 = *(const ulonglong2*)(w0 + d);
        ulonglong2 wp1 = *(const ulonglong2*)(w1 + d);
        aq0 = ffma2(a.x, wp0.x, aq0);
        aq1 = ffma2(a.x, wp1.x, aq1);
        aq0 = ffma2(a.y, wp0.y, aq0);
        aq1 = ffma2(a.y, wp1.y, aq1);
      }
      float2 t0 = unpack2(aq0), t1 = unpack2(aq1);
      cq0 = t0.x + t0.y;
      cq1 = t1.x + t1.y;
    }
    __syncthreads();
    // ck = out @ cWk_h + cbk_h
    STAGET(p.cWk + h * 64, 256);
    __syncthreads();
    proj_store(my_out, s_w, p.cbk + h * 64, lane, my_k, 0);
    __syncthreads();
    // cv
    STAGET(p.cWv + h * 64, 256);
    __syncthreads();
    proj_store(my_out, s_w, p.cbv + h * 64, lane, my_v, 0);
    __syncthreads();
    // scores over 8 keys (warp-reduced dots), softmax, ctx
    float e[8];
    #pragma unroll
    for (int k = 0; k < 8; k++) {
      float pk = cq0 * my_k[k * 64 + lane] + cq1 * my_k[k * 64 + lane + 32];
      #pragma unroll
      for (int o = 16; o > 0; o >>= 1) pk += __shfl_xor_sync(0xffffffffu, pk, o);
      e[k] = pk * 0.125f;
    }
    float mm = e[0];
    #pragma unroll
    for (int k = 1; k < 8; k++) mm = fmaxf(mm, e[k]);
    float prb[8], sum = 0.f;
    #pragma unroll
    for (int k = 0; k < 8; k++) { prb[k] = __expf(e[k] - mm); sum += prb[k]; }
    float inv = __fdividef(1.f, sum);
    float cx0 = 0.f, cx1 = 0.f;
    #pragma unroll
    for (int k = 0; k < 8; k++) {
      float pk = prb[k] * inv;
      cx0 = fmaf(pk, my_v[k * 64 + lane], cx0);
      cx1 = fmaf(pk, my_v[k * 64 + lane + 32], cx1);
    }
    my_q[lane] = cx0;
    my_q[lane + 32] = cx1;
    __syncwarp();
    // ca += ctx @ cWo_h   (+ cbo at h==0)
    STAGET(p.cWo + h * 4096, 64);
    __syncthreads();
    {
      ull ac0, ac1;
      if (h == 0) {
        ac0 = pack2(p.cbo[lane], ca0);
        ac1 = pack2(p.cbo[lane + 32], ca1);
      } else {
        ac0 = pack2(ca0, 0.f);
        ac1 = pack2(ca1, 0.f);
      }
      const float* w0 = s_w + lane * WSTRIDE;
      const float* w1 = s_w + (lane + 32) * WSTRIDE;
      #pragma unroll
      for (int d = 0; d < 64; d += 4) {
        ulonglong2 a = *(const ulonglong2*)(my_q + d);
        ulonglong2 wp0 = *(const ulonglong2*)(w0 + d);
        ulonglong2 wp1 = *(const ulonglong2*)(w1 + d);
        ac0 = ffma2(a.x, wp0.x, ac0);
        ac1 = ffma2(a.x, wp1.x, ac1);
        ac0 = ffma2(a.y, wp0.y, ac0);
        ac1 = ffma2(a.y, wp1.y, ac1);
      }
      float2 t0 = unpack2(ac0), t1 = unpack2(ac1);
      ca0 = t0.x + t0.y;
      ca1 = t1.x + t1.y;
    }
    __syncthreads();
  }

  // color = relu(ca) @ Wc + bc
  {
    float r0 = fmaxf(ca0, 0.f), r1 = fmaxf(ca1, 0.f);
    #pragma unroll
    for (int t = 0; t < 3; t++) {
      float part = r0 * p.Wc[lane * 3 + t] + r1 * p.Wc[(lane + 32) * 3 + t];
      #pragma unroll
      for (int o = 16; o > 0; o >>= 1) part += __shfl_xor_sync(0xffffffffu, part, o);
      if (lane == 0) p.o_color[(size_t)b * 3 + t] = part + p.bc[t];
    }
  }
}

extern "C" void kernel_launch(void* const* d_in, const int* in_sizes, int n_in,
                              void* d_out, int out_size) {
  Params p;
  p.query = (const float*)d_in[0];
  p.latent = (const float*)d_in[1];
  p.W1 = (const float*)d_in[2];
  p.b1 = (const float*)d_in[3];
  p.Wq = (const float*)d_in[4];
  p.bq = (const float*)d_in[5];
  p.Wk = (const float*)d_in[6];
  p.bk = (const float*)d_in[7];
  p.Wv = (const float*)d_in[8];
  p.bv = (const float*)d_in[9];
  p.Wo = (const float*)d_in[10];
  p.bo = (const float*)d_in[11];
  p.fW1 = (const float*)d_in[12];
  p.fb1 = (const float*)d_in[13];
  p.fW2 = (const float*)d_in[14];
  p.fb2 = (const float*)d_in[15];
  p.g1 = (const float*)d_in[16];
  p.be1 = (const float*)d_in[17];
  p.g2 = (const float*)d_in[18];
  p.be2 = (const float*)d_in[19];
  p.cWq = (const float*)d_in[20];
  p.cbq = (const float*)d_in[21];
  p.cWk = (const float*)d_in[22];
  p.cbk = (const float*)d_in[23];
  p.cWv = (const float*)d_in[24];
  p.cbv = (const float*)d_in[25];
  p.cWo = (const float*)d_in[26];
  p.cbo = (const float*)d_in[27];
  p.Wc = (const float*)d_in[28];
  p.bc = (const float*)d_in[29];
  p.Ws = (const float*)d_in[30];
  p.bs = (const float*)d_in[31];

  float* o = (float*)d_out;
  p.o_color = o;                                    // [B,1,3]
  p.o_sigma = o + (size_t)B_TOTAL * 3;              // [B,1]
  p.o_out = o + (size_t)B_TOTAL * 4;                // [B,8,64]
  p.o_attn = o + (size_t)B_TOTAL * 4 + (size_t)B_TOTAL * 512;  // [B,4,4,8,8]

  cudaFuncSetAttribute(rt_kernel, cudaFuncAttributeMaxDynamicSharedMemorySize,
                       SMEM_BYTES);
  rt_kernel<<<NBLOCKS, NTHREADS, SMEM_BYTES>>>(p);
}

// round 5
// speedup vs baseline: 1.4279x; 1.0487x over previous
#include <cuda_runtime.h>

typedef unsigned long long ull;

#define NTHREADS 256
#define RAYS 8
#define NBLOCKS 4096          // 32768 / 8
#define B_TOTAL 32768

#define NW 68                 // padded column stride (floats) for transposed weights

// dynamic shared layout (in floats): three transposed 64x64 weight buffers
#define OFF_W0   0                         // 64*68 = 4352
#define OFF_W1   4352
#define OFF_W2   8704
#define OFF_OUT  13056                     // per-ray out state 8x(8x64)  (4096)
#define OFF_A    (OFF_OUT + 4096)          // per-ray attn accum          (4096)
#define OFF_QKV  (OFF_A + 4096)            // per-ray Q,K,V 8x3x(8x64)    (12288)
#define OFF_P    (OFF_QKV + 12288)         // per-ray probs/query 8x64    (512)
#define SMEM_FLOATS (OFF_P + 512)
#define SMEM_BYTES  (SMEM_FLOATS * 4)

struct Params {
  const float *query, *latent, *W1, *b1;
  const float *Wq, *bq, *Wk, *bk, *Wv, *bv, *Wo, *bo;
  const float *fW1, *fb1, *fW2, *fb2, *g1, *be1, *g2, *be2;
  const float *cWq, *cbq, *cWk, *cbk, *cWv, *cbv, *cWo, *cbo;
  const float *Wc, *bc, *Ws, *bs;
  float *o_color, *o_sigma, *o_out, *o_attn;
};

__device__ __forceinline__ ull ffma2(ull a, ull b, ull c) {
  ull d;
  asm("fma.rn.f32x2 %0, %1, %2, %3;" : "=l"(d) : "l"(a), "l"(b), "l"(c));
  return d;
}
__device__ __forceinline__ ull pack2(float lo, float hi) {
  ull d;
  asm("mov.b64 %0, {%1, %2};" : "=l"(d) : "f"(lo), "f"(hi));
  return d;
}
__device__ __forceinline__ float2 unpack2(ull v) {
  float lo, hi;
  asm("mov.b64 {%0, %1}, %2;" : "=f"(lo), "=f"(hi) : "l"(v));
  return make_float2(lo, hi);
}

// Stage a 64x64 weight block TRANSPOSED into dst[j*NW + d].
// Vectorized: per iteration 4 coalesced LDG.32 (lanes sweep j) + 1 conflict-free
// STS.128 (block index 17*j + d/4 -> distinct bank groups within 8-lane phases).
__device__ __forceinline__ void stage_t(const float* __restrict__ src, int stride,
                                        float* __restrict__ dst, int tid) {
  #pragma unroll
  for (int it = 0; it < 4; it++) {
    int idx = tid + it * NTHREADS;
    int j = idx & 63, d0 = (idx >> 6) << 2;
    float4 v;
    v.x = src[(d0 + 0) * stride + j];
    v.y = src[(d0 + 1) * stride + j];
    v.z = src[(d0 + 2) * stride + j];
    v.w = src[(d0 + 3) * stride + j];
    *(float4*)(dst + j * NW + d0) = v;
  }
}

// dst(8x64)[:, {lane, lane+32}] = act(8x64) @ w(64x64) with packed even/odd-d
// partials. wt transposed+padded: wt[c*NW + d].
__device__ __forceinline__ void gemm8t(const float* __restrict__ act,
                                       const float* __restrict__ wt,
                                       int lane, ull acc0[8], ull acc1[8]) {
  const float* w0 = wt + lane * NW;
  const float* w1 = wt + (lane + 32) * NW;
  #pragma unroll 2
  for (int d = 0; d < 64; d += 4) {
    ulonglong2 wp0 = *(const ulonglong2*)(w0 + d);
    ulonglong2 wp1 = *(const ulonglong2*)(w1 + d);
    #pragma unroll
    for (int s = 0; s < 8; s++) {
      ulonglong2 a = *(const ulonglong2*)(act + s * 64 + d);
      acc0[s] = ffma2(a.x, wp0.x, acc0[s]);
      acc1[s] = ffma2(a.x, wp1.x, acc1[s]);
      acc0[s] = ffma2(a.y, wp0.y, acc0[s]);
      acc1[s] = ffma2(a.y, wp1.y, acc1[s]);
    }
  }
}

// Fused 3-matrix projection: ONE pass over act computes Q, K, V head blocks.
// Act smem traffic amortized 3x (the binding resource).
__device__ __forceinline__ void qkv_gemm(const float* __restrict__ act,
                                         const float* __restrict__ wq,
                                         const float* __restrict__ wk,
                                         const float* __restrict__ wv,
                                         const float* bq, const float* bk,
                                         const float* bv, int lane,
                                         float* dq, float* dk, float* dv) {
  ull A0[8], A1[8], B0[8], B1[8], C0[8], C1[8];
  {
    float q0 = bq[lane], q1 = bq[lane + 32];
    float k0 = bk[lane], k1 = bk[lane + 32];
    float v0 = bv[lane], v1 = bv[lane + 32];
    #pragma unroll
    for (int s = 0; s < 8; s++) {
      A0[s] = pack2(q0, 0.f); A1[s] = pack2(q1, 0.f);
      B0[s] = pack2(k0, 0.f); B1[s] = pack2(k1, 0.f);
      C0[s] = pack2(v0, 0.f); C1[s] = pack2(v1, 0.f);
    }
  }
  const float* q0p = wq + lane * NW; const float* q1p = wq + (lane + 32) * NW;
  const float* k0p = wk + lane * NW; const float* k1p = wk + (lane + 32) * NW;
  const float* v0p = wv + lane * NW; const float* v1p = wv + (lane + 32) * NW;
  #pragma unroll 1
  for (int d = 0; d < 64; d += 4) {
    ulonglong2 wq0 = *(const ulonglong2*)(q0p + d);
    ulonglong2 wq1 = *(const ulonglong2*)(q1p + d);
    ulonglong2 wk0 = *(const ulonglong2*)(k0p + d);
    ulonglong2 wk1 = *(const ulonglong2*)(k1p + d);
    ulonglong2 wv0 = *(const ulonglong2*)(v0p + d);
    ulonglong2 wv1 = *(const ulonglong2*)(v1p + d);
    #pragma unroll
    for (int s = 0; s < 8; s++) {
      ulonglong2 a = *(const ulonglong2*)(act + s * 64 + d);
      A0[s] = ffma2(a.x, wq0.x, A0[s]);
      A1[s] = ffma2(a.x, wq1.x, A1[s]);
      B0[s] = ffma2(a.x, wk0.x, B0[s]);
      B1[s] = ffma2(a.x, wk1.x, B1[s]);
      C0[s] = ffma2(a.x, wv0.x, C0[s]);
      C1[s] = ffma2(a.x, wv1.x, C1[s]);
      A0[s] = ffma2(a.y, wq0.y, A0[s]);
      A1[s] = ffma2(a.y, wq1.y, A1[s]);
      B0[s] = ffma2(a.y, wk0.y, B0[s]);
      B1[s] = ffma2(a.y, wk1.y, B1[s]);
      C0[s] = ffma2(a.y, wv0.y, C0[s]);
      C1[s] = ffma2(a.y, wv1.y, C1[s]);
    }
  }
  #pragma unroll
  for (int s = 0; s < 8; s++) {
    float2 x;
    x = unpack2(A0[s]); dq[s * 64 + lane] = x.x + x.y;
    x = unpack2(A1[s]); dq[s * 64 + lane + 32] = x.x + x.y;
    x = unpack2(B0[s]); dk[s * 64 + lane] = x.x + x.y;
    x = unpack2(B1[s]); dk[s * 64 + lane + 32] = x.x + x.y;
    x = unpack2(C0[s]); dv[s * 64 + lane] = x.x + x.y;
    x = unpack2(C1[s]); dv[s * 64 + lane + 32] = x.x + x.y;
  }
}

// Fused 2-matrix projection (cross-attn K and V share act).
__device__ __forceinline__ void kv_gemm(const float* __restrict__ act,
                                        const float* __restrict__ wk,
                                        const float* __restrict__ wv,
                                        const float* bk, const float* bv,
                                        int lane, float* dk, float* dv) {
  ull B0[8], B1[8], C0[8], C1[8];
  {
    float k0 = bk[lane], k1 = bk[lane + 32];
    float v0 = bv[lane], v1 = bv[lane + 32];
    #pragma unroll
    for (int s = 0; s < 8; s++) {
      B0[s] = pack2(k0, 0.f); B1[s] = pack2(k1, 0.f);
      C0[s] = pack2(v0, 0.f); C1[s] = pack2(v1, 0.f);
    }
  }
  const float* k0p = wk + lane * NW; const float* k1p = wk + (lane + 32) * NW;
  const float* v0p = wv + lane * NW; const float* v1p = wv + (lane + 32) * NW;
  #pragma unroll 1
  for (int d = 0; d < 64; d += 4) {
    ulonglong2 wk0 = *(const ulonglong2*)(k0p + d);
    ulonglong2 wk1 = *(const ulonglong2*)(k1p + d);
    ulonglong2 wv0 = *(const ulonglong2*)(v0p + d);
    ulonglong2 wv1 = *(const ulonglong2*)(v1p + d);
    #pragma unroll
    for (int s = 0; s < 8; s++) {
      ulonglong2 a = *(const ulonglong2*)(act + s * 64 + d);
      B0[s] = ffma2(a.x, wk0.x, B0[s]);
      B1[s] = ffma2(a.x, wk1.x, B1[s]);
      C0[s] = ffma2(a.x, wv0.x, C0[s]);
      C1[s] = ffma2(a.x, wv1.x, C1[s]);
      B0[s] = ffma2(a.y, wk0.y, B0[s]);
      B1[s] = ffma2(a.y, wk1.y, B1[s]);
      C0[s] = ffma2(a.y, wv0.y, C0[s]);
      C1[s] = ffma2(a.y, wv1.y, C1[s]);
    }
  }
  #pragma unroll
  for (int s = 0; s < 8; s++) {
    float2 x;
    x = unpack2(B0[s]); dk[s * 64 + lane] = x.x + x.y;
    x = unpack2(B1[s]); dk[s * 64 + lane + 32] = x.x + x.y;
    x = unpack2(C0[s]); dv[s * 64 + lane] = x.x + x.y;
    x = unpack2(C1[s]); dv[s * 64 + lane + 32] = x.x + x.y;
  }
}

// full projection with bias, optional relu, store to dst (warp-local rows)
__device__ __forceinline__ void proj_store(const float* act, const float* wt,
                                           const float* bias, int lane,
                                           float* dst, int do_relu) {
  ull a0[8], a1[8];
  float b0 = bias[lane], b1 = bias[lane + 32];
  #pragma unroll
  for (int s = 0; s < 8; s++) { a0[s] = pack2(b0, 0.f); a1[s] = pack2(b1, 0.f); }
  gemm8t(act, wt, lane, a0, a1);
  #pragma unroll
  for (int s = 0; s < 8; s++) {
    float2 x = unpack2(a0[s]);
    float2 y = unpack2(a1[s]);
    float r0 = x.x + x.y, r1 = y.x + y.y;
    if (do_relu) { r0 = fmaxf(r0, 0.f); r1 = fmaxf(r1, 0.f); }
    dst[s * 64 + lane] = r0;
    dst[s * 64 + lane + 32] = r1;
  }
}

// LayerNorm of v (8 rows; this lane holds cols lane and lane+32), write to dst
__device__ __forceinline__ void layernorm8(const float v[16], const float* g,
                                           const float* be, int lane, float* dst) {
  float gg0 = g[lane], gg1 = g[lane + 32];
  float bb0 = be[lane], bb1 = be[lane + 32];
  #pragma unroll
  for (int s = 0; s < 8; s++) {
    float sum = v[2 * s] + v[2 * s + 1];
    #pragma unroll
    for (int o = 16; o > 0; o >>= 1) sum += __shfl_xor_sync(0xffffffffu, sum, o);
    float mean = sum * 0.015625f;
    float d0 = v[2 * s] - mean, d1 = v[2 * s + 1] - mean;
    float vs = d0 * d0 + d1 * d1;
    #pragma unroll
    for (int o = 16; o > 0; o >>= 1) vs += __shfl_xor_sync(0xffffffffu, vs, o);
    float rstd = rsqrtf(vs * 0.015625f + 1e-5f);
    dst[s * 64 + lane] = d0 * rstd * gg0 + bb0;
    dst[s * 64 + lane + 32] = d1 * rstd * gg1 + bb1;
  }
}

__global__ void __launch_bounds__(NTHREADS, 1) rt_kernel(Params p) {
  extern __shared__ float sm[];
  const int tid = threadIdx.x;
  const int warp = tid >> 5, lane = tid & 31;
  const int b = blockIdx.x * RAYS + warp;

  float* s_w0 = sm + OFF_W0;
  float* s_w1 = sm + OFF_W1;
  float* s_w2 = sm + OFF_W2;
  float* s_out = sm + OFF_OUT;
  float* s_a = sm + OFF_A;
  float* s_qkv = sm + OFF_QKV;
  float* s_p = sm + OFF_P;

  float* my_out = s_out + warp * 512;
  float* my_a = s_a + warp * 512;
  float* my_q = s_qkv + warp * 1536;
  float* my_k = my_q + 512;
  float* my_v = my_q + 1024;
  float* my_p = s_p + warp * 64;

  // ---------------- stage 0: out = relu(latent @ W1 + b1) ----------------
  {
    ull a0[8], a1[8];
    float b0v = p.b1[lane], b1v = p.b1[lane + 32];
    #pragma unroll
    for (int s = 0; s < 8; s++) { a0[s] = pack2(b0v, 0.f); a1[s] = pack2(b1v, 0.f); }
    float* s_lat = s_qkv;  // reuse QKV space as latent chunk staging
    for (int kc = 0; kc < 8; kc++) {
      stage_t(p.W1 + kc * 4096, 64, s_w0, tid);
      for (int i = tid; i < 4096; i += NTHREADS) {
        int r = i >> 9, rem = i & 511, s = rem >> 6, d = rem & 63;
        s_lat[i] = p.latent[(size_t)(blockIdx.x * RAYS + r) * 4096 +
                            (size_t)s * 512 + kc * 64 + d];
      }
      __syncthreads();
      gemm8t(s_lat + warp * 512, s_w0, lane, a0, a1);
      __syncthreads();
    }
    #pragma unroll
    for (int s = 0; s < 8; s++) {
      float2 x = unpack2(a0[s]);
      float2 y = unpack2(a1[s]);
      my_out[s * 64 + lane] = fmaxf(x.x + x.y, 0.f);
      my_out[s * 64 + lane + 32] = fmaxf(y.x + y.y, 0.f);
    }
  }
  __syncthreads();

  // ---------------- 4 transformer layers ----------------
  for (int l = 0; l < 4; l++) {
    for (int h = 0; h < 4; h++) {
      // stage Q, K, V head blocks, then ONE fused act pass
      stage_t(p.Wq + l * 16384 + h * 64, 256, s_w0, tid);
      stage_t(p.Wk + l * 16384 + h * 64, 256, s_w1, tid);
      stage_t(p.Wv + l * 16384 + h * 64, 256, s_w2, tid);
      __syncthreads();
      qkv_gemm(my_out, s_w0, s_w1, s_w2,
               p.bq + l * 256 + h * 64, p.bk + l * 256 + h * 64,
               p.bv + l * 256 + h * 64, lane, my_q, my_k, my_v);
      __syncwarp();

      // ---- attention (8x8, warp-local) ----
      {
        float pr[2];
        #pragma unroll
        for (int u = 0; u < 2; u++) {
          int idx = lane + u * 32;
          int q = idx >> 3, k = idx & 7;
          const float* qr = my_q + q * 64;
          const float* kr = my_k + k * 64;
          ull acc = pack2(0.f, 0.f);
          #pragma unroll
          for (int j = 0; j < 64; j += 4) {
            ulonglong2 qq = *(const ulonglong2*)(qr + j);
            ulonglong2 kk = *(const ulonglong2*)(kr + j);
            acc = ffma2(qq.x, kk.x, acc);
            acc = ffma2(qq.y, kk.y, acc);
          }
          float2 t = unpack2(acc);
          float sc = (t.x + t.y) * 0.125f;
          float m = sc;
          m = fmaxf(m, __shfl_xor_sync(0xffffffffu, m, 1));
          m = fmaxf(m, __shfl_xor_sync(0xffffffffu, m, 2));
          m = fmaxf(m, __shfl_xor_sync(0xffffffffu, m, 4));
          float e = __expf(sc - m);
          float se = e;
          se += __shfl_xor_sync(0xffffffffu, se, 1);
          se += __shfl_xor_sync(0xffffffffu, se, 2);
          se += __shfl_xor_sync(0xffffffffu, se, 4);
          pr[u] = __fdividef(e, se);
        }
        my_p[lane] = pr[0];
        my_p[lane + 32] = pr[1];
        {
          size_t ab = (size_t)b * 1024 + (size_t)l * 256 + h * 64;
          p.o_attn[ab + lane] = pr[0];
          p.o_attn[ab + lane + 32] = pr[1];
        }
        __syncwarp();
        // context = prob @ V
        float cx[16];
        #pragma unroll
        for (int i = 0; i < 16; i++) cx[i] = 0.f;
        #pragma unroll
        for (int k = 0; k < 8; k++) {
          float vx = my_v[k * 64 + lane];
          float vy = my_v[k * 64 + lane + 32];
          #pragma unroll
          for (int q = 0; q < 8; q++) {
            float pk = my_p[q * 8 + k];
            cx[2 * q] = fmaf(pk, vx, cx[2 * q]);
            cx[2 * q + 1] = fmaf(pk, vy, cx[2 * q + 1]);
          }
        }
        __syncwarp();
        #pragma unroll
        for (int q = 0; q < 8; q++) {
          my_q[q * 64 + lane] = cx[2 * q];       // Q slot reused as context
          my_q[q * 64 + lane + 32] = cx[2 * q + 1];
        }
        __syncwarp();
      }

      // ---- out-proj (head block of Wo), accumulate into s_a ----
      __syncthreads();
      stage_t(p.Wo + l * 16384 + h * 4096, 64, s_w0, tid);
      __syncthreads();
      {
        ull a0[8], a1[8];
        if (h == 0) {
          float o0 = p.bo[l * 64 + lane], o1 = p.bo[l * 64 + lane + 32];
          #pragma unroll
          for (int s = 0; s < 8; s++) { a0[s] = pack2(o0, 0.f); a1[s] = pack2(o1, 0.f); }
        } else {
          #pragma unroll
          for (int s = 0; s < 8; s++) {
            a0[s] = pack2(my_a[s * 64 + lane], 0.f);
            a1[s] = pack2(my_a[s * 64 + lane + 32], 0.f);
          }
        }
        gemm8t(my_q, s_w0, lane, a0, a1);
        #pragma unroll
        for (int s = 0; s < 8; s++) {
          float2 x = unpack2(a0[s]);
          float2 y = unpack2(a1[s]);
          my_a[s * 64 + lane] = x.x + x.y;
          my_a[s * 64 + lane + 32] = y.x + y.y;
        }
      }
      __syncthreads();
    }  // heads

    // ---- LN1: out = LN(a + out) ----
    {
      float v[16];
      #pragma unroll
      for (int s = 0; s < 8; s++) {
        v[2 * s] = my_a[s * 64 + lane] + my_out[s * 64 + lane];
        v[2 * s + 1] = my_a[s * 64 + lane + 32] + my_out[s * 64 + lane + 32];
      }
      layernorm8(v, p.g1 + l * 64, p.be1 + l * 64, lane, my_out);
    }
    // ---- FF1 ----
    stage_t(p.fW1 + l * 4096, 64, s_w0, tid);
    __syncthreads();   // also makes LN1's my_out writes CTA-visible
    proj_store(my_out, s_w0, p.fb1 + l * 64, lane, my_q, 1);
    __syncthreads();
    // ---- FF2 + LN2 ----
    stage_t(p.fW2 + l * 4096, 64, s_w0, tid);
    __syncthreads();
    {
      ull a0[8], a1[8];
      float f0 = p.fb2[l * 64 + lane], f1 = p.fb2[l * 64 + lane + 32];
      #pragma unroll
      for (int s = 0; s < 8; s++) { a0[s] = pack2(f0, 0.f); a1[s] = pack2(f1, 0.f); }
      gemm8t(my_q, s_w0, lane, a0, a1);
      float v[16];
      #pragma unroll
      for (int s = 0; s < 8; s++) {
        float2 x = unpack2(a0[s]);
        float2 y = unpack2(a1[s]);
        v[2 * s] = x.x + x.y + my_out[s * 64 + lane];
        v[2 * s + 1] = y.x + y.y + my_out[s * 64 + lane + 32];
      }
      layernorm8(v, p.g2 + l * 64, p.be2 + l * 64, lane, my_out);
    }
    __syncthreads();
  }  // layers

  // ---------------- sigma = max_s(out) @ Ws + bs ----------------
  {
    float m0 = my_out[lane], m1 = my_out[lane + 32];
    #pragma unroll
    for (int s = 1; s < 8; s++) {
      m0 = fmaxf(m0, my_out[s * 64 + lane]);
      m1 = fmaxf(m1, my_out[s * 64 + lane + 32]);
    }
    float part = m0 * p.Ws[lane] + m1 * p.Ws[lane + 32];
    #pragma unroll
    for (int o = 16; o > 0; o >>= 1) part += __shfl_xor_sync(0xffffffffu, part, o);
    if (lane == 0) p.o_sigma[b] = part + p.bs[0];
  }

  // ---------------- write out state ----------------
  #pragma unroll
  for (int s = 0; s < 8; s++) {
    p.o_out[(size_t)b * 512 + s * 64 + lane] = my_out[s * 64 + lane];
    p.o_out[(size_t)b * 512 + s * 64 + lane + 32] = my_out[s * 64 + lane + 32];
  }

  // ---------------- cross attention + color ----------------
  my_p[lane] = p.query[(size_t)b * 64 + lane];
  my_p[lane + 32] = p.query[(size_t)b * 64 + lane + 32];
  __syncwarp();

  float ca0 = 0.f, ca1 = 0.f;
  for (int h = 0; h < 4; h++) {
    // stage cWq, cWk, cWv together; one sync
    stage_t(p.cWq + h * 64, 256, s_w2, tid);
    stage_t(p.cWk + h * 64, 256, s_w0, tid);
    stage_t(p.cWv + h * 64, 256, s_w1, tid);
    __syncthreads();
    // cq = query @ cWq_h + cbq_h   (1 row)
    float cq0, cq1;
    {
      ull aq0 = pack2(p.cbq[h * 64 + lane], 0.f);
      ull aq1 = pack2(p.cbq[h * 64 + lane + 32], 0.f);
      const float* w0 = s_w2 + lane * NW;
      const float* w1 = s_w2 + (lane + 32) * NW;
      #pragma unroll
      for (int d = 0; d < 64; d += 4) {
        ulonglong2 a = *(const ulonglong2*)(my_p + d);
        ulonglong2 wp0 = *(const ulonglong2*)(w0 + d);
        ulonglong2 wp1 = *(const ulonglong2*)(w1 + d);
        aq0 = ffma2(a.x, wp0.x, aq0);
        aq1 = ffma2(a.x, wp1.x, aq1);
        aq0 = ffma2(a.y, wp0.y, aq0);
        aq1 = ffma2(a.y, wp1.y, aq1);
      }
      float2 t0 = unpack2(aq0), t1 = unpack2(aq1);
      cq0 = t0.x + t0.y;
      cq1 = t1.x + t1.y;
    }
    // fused cK + cV projection (shared act = my_out)
    kv_gemm(my_out, s_w0, s_w1, p.cbk + h * 64, p.cbv + h * 64, lane, my_k, my_v);
    __syncwarp();
    // scores over 8 keys (warp-reduced dots), softmax, ctx
    float e[8];
    #pragma unroll
    for (int k = 0; k < 8; k++) {
      float pk = cq0 * my_k[k * 64 + lane] + cq1 * my_k[k * 64 + lane + 32];
      #pragma unroll
      for (int o = 16; o > 0; o >>= 1) pk += __shfl_xor_sync(0xffffffffu, pk, o);
      e[k] = pk * 0.125f;
    }
    float mm = e[0];
    #pragma unroll
    for (int k = 1; k < 8; k++) mm = fmaxf(mm, e[k]);
    float prb[8], sum = 0.f;
    #pragma unroll
    for (int k = 0; k < 8; k++) { prb[k] = __expf(e[k] - mm); sum += prb[k]; }
    float inv = __fdividef(1.f, sum);
    float cx0 = 0.f, cx1 = 0.f;
    #pragma unroll
    for (int k = 0; k < 8; k++) {
      float pk = prb[k] * inv;
      cx0 = fmaf(pk, my_v[k * 64 + lane], cx0);
      cx1 = fmaf(pk, my_v[k * 64 + lane + 32], cx1);
    }
    my_q[lane] = cx0;
    my_q[lane + 32] = cx1;
    __syncwarp();
    __syncthreads();
    // ca += ctx @ cWo_h   (+ cbo at h==0)
    stage_t(p.cWo + h * 4096, 64, s_w0, tid);
    __syncthreads();
    {
      ull ac0, ac1;
      if (h == 0) {
        ac0 = pack2(p.cbo[lane], ca0);
        ac1 = pack2(p.cbo[lane + 32], ca1);
      } else {
        ac0 = pack2(ca0, 0.f);
        ac1 = pack2(ca1, 0.f);
      }
      const float* w0 = s_w0 + lane * NW;
      const float* w1 = s_w0 + (lane + 32) * NW;
      #pragma unroll
      for (int d = 0; d < 64; d += 4) {
        ulonglong2 a = *(const ulonglong2*)(my_q + d);
        ulonglong2 wp0 = *(const ulonglong2*)(w0 + d);
        ulonglong2 wp1 = *(const ulonglong2*)(w1 + d);
        ac0 = ffma2(a.x, wp0.x, ac0);
        ac1 = ffma2(a.x, wp1.x, ac1);
        ac0 = ffma2(a.y, wp0.y, ac0);
        ac1 = ffma2(a.y, wp1.y, ac1);
      }
      float2 t0 = unpack2(ac0), t1 = unpack2(ac1);
      ca0 = t0.x + t0.y;
      ca1 = t1.x + t1.y;
    }
    __syncthreads();
  }

  // color = relu(ca) @ Wc + bc
  {
    float r0 = fmaxf(ca0, 0.f), r1 = fmaxf(ca1, 0.f);
    #pragma unroll
    for (int t = 0; t < 3; t++) {
      float part = r0 * p.Wc[lane * 3 + t] + r1 * p.Wc[(lane + 32) * 3 + t];
      #pragma unroll
      for (int o = 16; o > 0; o >>= 1) part += __shfl_xor_sync(0xffffffffu, part, o);
      if (lane == 0) p.o_color[(size_t)b * 3 + t] = part + p.bc[t];
    }
  }
}

extern "C" void kernel_launch(void* const* d_in, const int* in_sizes, int n_in,
                              void* d_out, int out_size) {
  Params p;
  p.query = (const float*)d_in[0];
  p.latent = (const float*)d_in[1];
  p.W1 = (const float*)d_in[2];
  p.b1 = (const float*)d_in[3];
  p.Wq = (const float*)d_in[4];
  p.bq = (const float*)d_in[5];
  p.Wk = (const float*)d_in[6];
  p.bk = (const float*)d_in[7];
  p.Wv = (const float*)d_in[8];
  p.bv = (const float*)d_in[9];
  p.Wo = (const float*)d_in[10];
  p.bo = (const float*)d_in[11];
  p.fW1 = (const float*)d_in[12];
  p.fb1 = (const float*)d_in[13];
  p.fW2 = (const float*)d_in[14];
  p.fb2 = (const float*)d_in[15];
  p.g1 = (const float*)d_in[16];
  p.be1 = (const float*)d_in[17];
  p.g2 = (const float*)d_in[18];
  p.be2 = (const float*)d_in[19];
  p.cWq = (const float*)d_in[20];
  p.cbq = (const float*)d_in[21];
  p.cWk = (const float*)d_in[22];
  p.cbk = (const float*)d_in[23];
  p.cWv = (const float*)d_in[24];
  p.cbv = (const float*)d_in[25];
  p.cWo = (const float*)d_in[26];
  p.cbo = (const float*)d_in[27];
  p.Wc = (const float*)d_in[28];
  p.bc = (const float*)d_in[29];
  p.Ws = (const float*)d_in[30];
  p.bs = (const float*)d_in[31];

  float* o = (float*)d_out;
  p.o_color = o;                                    // [B,1,3]
  p.o_sigma = o + (size_t)B_TOTAL * 3;              // [B,1]
  p.o_out = o + (size_t)B_TOTAL * 4;                // [B,8,64]
  p.o_attn = o + (size_t)B_TOTAL * 4 + (size_t)B_TOTAL * 512;  // [B,4,4,8,8]

  cudaFuncSetAttribute(rt_kernel, cudaFuncAttributeMaxDynamicSharedMemorySize,
                       SMEM_BYTES);
  rt_kernel<<<NBLOCKS, NTHREADS, SMEM_BYTES>>>(p);
}